// round 3
// baseline (speedup 1.0000x reference)
#include <cuda_runtime.h>
#include <math.h>

// Problem constants: C=128, B=32, H=W=64.
// Per-LSTM: N = 2048 rows, T = 64 steps, C = 128 channels, 4C = 512 gates.
#define NPLANE 16777216  // 2048*64*128

// Scratch (device globals; no runtime allocation).
// g_xT[0]: vertical layout  x[(b*64+h)*64 + w][c]
// g_xT[1]: horizontal layout x[(b*64+w)*64 + h][c]
__device__ float g_xT[2][NPLANE];
// g_H[l][(n*64+t)*128 + c] : LSTM hidden outputs, l = {vf, vb, hf, hb}
__device__ float g_H[4][NPLANE];

struct LstmParams {
    const float* Wih[4];
    const float* Whh[4];
    const float* bias[4];
};
struct ConvParams {
    const float* w[4];
    const float* b[4];
};

// --------------------------------------------------------------------------
// Kernel 1: transpose x[B,C,H,W] into the two [n][t][c] scan layouts.
// One CTA per (b,h) slab; smem tile [c][w] with pad-65 for conflict-free
// transposed reads.
// --------------------------------------------------------------------------
__global__ __launch_bounds__(256) void transpose_kernel(const float* __restrict__ x) {
    __shared__ float s[128 * 65];
    int b = blockIdx.x >> 6;
    int h = blockIdx.x & 63;
    int tid = threadIdx.x;

    const float* xb = x + (size_t)b * 128 * 4096 + (size_t)h * 64;
    // coalesced loads: consecutive w
    for (int idx = tid; idx < 128 * 64; idx += 256) {
        int c = idx >> 6, w = idx & 63;
        s[c * 65 + w] = xb[(size_t)c * 4096 + w];
    }
    __syncthreads();

    // vertical: g_xT[0][((b*64+h)*64 + w)*128 + c]  (coalesced: consecutive c)
    float* xv = g_xT[0] + (size_t)(b * 64 + h) * 64 * 128;
    for (int idx = tid; idx < 128 * 64; idx += 256) {
        int w = idx >> 7, c = idx & 127;
        xv[w * 128 + c] = s[c * 65 + w];
    }
    // horizontal: g_xT[1][((b*64+w)*64 + h)*128 + c]
    float* xh = g_xT[1] + (size_t)b * 64 * 64 * 128 + (size_t)h * 128;
    for (int idx = tid; idx < 128 * 64; idx += 256) {
        int w = idx >> 7, c = idx & 127;
        xh[(size_t)w * 64 * 128 + c] = s[c * 65 + w];
    }
}

// --------------------------------------------------------------------------
// Gate nonlinearities. Full-precision-ish via __expf; numerically safe at
// saturation (exp -> 0 or inf gives exact 0/1 limits, no NaN).
// --------------------------------------------------------------------------
__device__ __forceinline__ float sigf(float x)  { return 1.0f / (1.0f + __expf(-x)); }
__device__ __forceinline__ float tanhf_(float x){ return 2.0f / (1.0f + __expf(-2.0f * x)) - 1.0f; }

// --------------------------------------------------------------------------
// Kernel 2: fused LSTM recurrence. grid = (256 row-groups, 4 LSTMs),
// 256 threads. Each CTA owns 8 rows for all 64 steps:
//   z = bias + x_t * Wih^T + h * Whh^T   (each thread: 2 gate cols x 8 rows)
//   gate combine: each thread owns 4 (row,channel) cells; c-state in regs.
// Wih/Whh are streamed from L2 (weights are L2-resident, 2 MB total).
// --------------------------------------------------------------------------
__global__ __launch_bounds__(256) void lstm_kernel(LstmParams P) {
    int lstm = blockIdx.y;
    int n0 = blockIdx.x * 8;

    const float* __restrict__ Wih  = P.Wih[lstm];
    const float* __restrict__ Whh  = P.Whh[lstm];
    const float* __restrict__ bias = P.bias[lstm];
    const float* __restrict__ xT   = g_xT[lstm >> 1];
    float* __restrict__ Hout       = g_H[lstm];
    const bool rev = (lstm & 1) != 0;

    __shared__ float xs[8 * 128];
    __shared__ float hs[8 * 128];
    __shared__ float zs[8 * 512];

    int tid = threadIdx.x;
    int g0 = tid * 2;
    float b0 = bias[g0], b1 = bias[g0 + 1];
    const float4* wihA = (const float4*)(Wih + (size_t)g0 * 128);
    const float4* wihB = (const float4*)(Wih + (size_t)(g0 + 1) * 128);
    const float4* whhA = (const float4*)(Whh + (size_t)g0 * 128);
    const float4* whhB = (const float4*)(Whh + (size_t)(g0 + 1) * 128);

    // combine-role mapping: row rr, channels cc..cc+3 (persistent c-state)
    int rr = tid >> 5;
    int lane = tid & 31;
    int cidx = lane;           // float4 index within a 128-float channel row
    float c0 = 0.f, c1 = 0.f, c2 = 0.f, c3 = 0.f;

    ((float4*)hs)[tid] = make_float4(0.f, 0.f, 0.f, 0.f);
    __syncthreads();

    const float4* xs4 = (const float4*)xs;
    const float4* hs4 = (const float4*)hs;

    for (int tt = 0; tt < 64; ++tt) {
        int t = rev ? 63 - tt : tt;

        // load x rows for this step (coalesced 512B per row)
        {
            const float4* xsrc = (const float4*)(xT + ((size_t)(n0 + rr) * 64 + t) * 128);
            ((float4*)(xs + rr * 128))[cidx] = xsrc[cidx];
        }
        __syncthreads();

        float acc0[8], acc1[8];
        #pragma unroll
        for (int r = 0; r < 8; r++) { acc0[r] = b0; acc1[r] = b1; }

        #pragma unroll 4
        for (int k = 0; k < 32; k++) {
            float4 wa = wihA[k], wb = wihB[k];
            #pragma unroll
            for (int r = 0; r < 8; r++) {
                float4 v = xs4[r * 32 + k];
                acc0[r] += v.x * wa.x + v.y * wa.y + v.z * wa.z + v.w * wa.w;
                acc1[r] += v.x * wb.x + v.y * wb.y + v.z * wb.z + v.w * wb.w;
            }
        }
        #pragma unroll 4
        for (int k = 0; k < 32; k++) {
            float4 wa = whhA[k], wb = whhB[k];
            #pragma unroll
            for (int r = 0; r < 8; r++) {
                float4 v = hs4[r * 32 + k];
                acc0[r] += v.x * wa.x + v.y * wa.y + v.z * wa.z + v.w * wa.w;
                acc1[r] += v.x * wb.x + v.y * wb.y + v.z * wb.z + v.w * wb.w;
            }
        }
        #pragma unroll
        for (int r = 0; r < 8; r++)
            ((float2*)(zs + r * 512))[tid] = make_float2(acc0[r], acc1[r]);
        __syncthreads();

        // gate combine: gates ordered (i, f, g, o) along the 512-dim
        {
            const float4* z4 = (const float4*)(zs + rr * 512);
            float4 zi = z4[cidx];
            float4 zf = z4[cidx + 32];
            float4 zg = z4[cidx + 64];
            float4 zo = z4[cidx + 96];

            c0 = sigf(zf.x) * c0 + sigf(zi.x) * tanhf_(zg.x);
            c1 = sigf(zf.y) * c1 + sigf(zi.y) * tanhf_(zg.y);
            c2 = sigf(zf.z) * c2 + sigf(zi.z) * tanhf_(zg.z);
            c3 = sigf(zf.w) * c3 + sigf(zi.w) * tanhf_(zg.w);

            float4 hv;
            hv.x = sigf(zo.x) * tanhf_(c0);
            hv.y = sigf(zo.y) * tanhf_(c1);
            hv.z = sigf(zo.z) * tanhf_(c2);
            hv.w = sigf(zo.w) * tanhf_(c3);

            ((float4*)(hs + rr * 128))[cidx] = hv;
            ((float4*)(Hout + ((size_t)(n0 + rr) * 64 + t) * 128))[cidx] = hv;
        }
        __syncthreads();
    }
}

// --------------------------------------------------------------------------
// Kernel 3: 1x1 conv. grid = (4096 position tiles, 4 outputs), 256 threads.
// CTA: 32 positions x 128 out-channels; thread: 4x4 register tile.
// H tile in smem (pad-132 keeps float4 reads 16B-aligned and bank-spread);
// W rows streamed from L2 per-thread (1 GB L2 traffic total, fine).
// Output k layout [b][o][s1][s2] matches [b][s1][s2][c] source indexing for
// both vertical (h,w) and horizontal (w,h) orientations automatically.
// --------------------------------------------------------------------------
__global__ __launch_bounds__(256) void conv_kernel(ConvParams P, float* __restrict__ out) {
    int k = blockIdx.y;                                   // 0:down 1:up 2:right 3:left
    int src = (k == 0) ? 1 : ((k == 1) ? 0 : k);          // H plane: down<-vb, up<-vf, right<-hf, left<-hb
    const float* __restrict__ Hg   = g_H[src];
    const float* __restrict__ W    = P.w[k];
    const float* __restrict__ bias = P.b[k];
    float* __restrict__ outk = out + (size_t)k * NPLANE;

    __shared__ float Hs[32 * 132];
    int tid = threadIdx.x;
    int p0 = blockIdx.x * 32;

    for (int idx = tid; idx < 32 * 128; idx += 256) {
        int p = idx >> 7, c = idx & 127;
        Hs[p * 132 + c] = Hg[(size_t)(p0 + p) * 128 + c];
    }
    __syncthreads();

    int tp = tid & 7;    // positions: tp + 8*i
    int to = tid >> 3;   // outputs:   to + 32*j

    float acc[4][4];
    #pragma unroll
    for (int j = 0; j < 4; j++) {
        float bj = bias[to + 32 * j];
        #pragma unroll
        for (int i = 0; i < 4; i++) acc[i][j] = bj;
    }

    #pragma unroll 4
    for (int k4 = 0; k4 < 32; k4++) {
        float4 wv[4];
        #pragma unroll
        for (int j = 0; j < 4; j++)
            wv[j] = *(const float4*)(W + (size_t)(to + 32 * j) * 128 + k4 * 4);
        #pragma unroll
        for (int i = 0; i < 4; i++) {
            float4 hv = *(const float4*)(Hs + (tp + 8 * i) * 132 + k4 * 4);
            #pragma unroll
            for (int j = 0; j < 4; j++)
                acc[i][j] += hv.x * wv[j].x + hv.y * wv[j].y + hv.z * wv[j].z + hv.w * wv[j].w;
        }
    }

    #pragma unroll
    for (int i = 0; i < 4; i++) {
        int p = p0 + tp + 8 * i;
        int b = p >> 12, q = p & 4095;
        float* ob = outk + (size_t)b * 128 * 4096 + q;
        #pragma unroll
        for (int j = 0; j < 4; j++)
            ob[(size_t)(to + 32 * j) * 4096] = acc[i][j];
    }
}

// --------------------------------------------------------------------------
// Launch. Inputs (metadata order):
// 0:x  1-3:vWih_f,vWhh_f,vb_f  4-6:vWih_b,vWhh_b,vb_b
// 7-9:hWih_f,hWhh_f,hb_f  10-12:hWih_b,hWhh_b,hb_b
// 13,14:w_down,b_down 15,16:w_up,b_up 17,18:w_right,b_right 19,20:w_left,b_left
// --------------------------------------------------------------------------
extern "C" void kernel_launch(void* const* d_in, const int* in_sizes, int n_in,
                              void* d_out, int out_size) {
    (void)in_sizes; (void)n_in; (void)out_size;
    const float* x = (const float*)d_in[0];

    LstmParams LP;
    for (int l = 0; l < 4; l++) {
        LP.Wih[l]  = (const float*)d_in[1 + 3 * l];
        LP.Whh[l]  = (const float*)d_in[2 + 3 * l];
        LP.bias[l] = (const float*)d_in[3 + 3 * l];
    }
    ConvParams CP;
    for (int k = 0; k < 4; k++) {
        CP.w[k] = (const float*)d_in[13 + 2 * k];
        CP.b[k] = (const float*)d_in[14 + 2 * k];
    }

    transpose_kernel<<<2048, 256>>>(x);
    lstm_kernel<<<dim3(256, 4), 256>>>(LP);
    conv_kernel<<<dim3(4096, 4), 256>>>(CP, (float*)d_out);
}

// round 5
// speedup vs baseline: 1.9492x; 1.9492x over previous
#include <cuda_runtime.h>
#include <math.h>

// Problem constants: C=128, B=32, H=W=64.
// Per-LSTM: N = 2048 rows, T = 64 steps, C = 128 channels, 4C = 512 gates.
#define NPLANE 16777216  // 2048*64*128

typedef unsigned long long ull;

// Scratch (device globals; no runtime allocation).
__device__ float g_xT[2][NPLANE];        // [0]=vertical [1]=horizontal, layout [n][t][c]
__device__ float g_H[4][NPLANE];         // LSTM hidden outputs {vf, vb, hf, hb}, [n][t][c]
__device__ float2 g_Wt[4][256 * 256];    // packed weights: [lstm][k*256 + p] = (W[p][k], W[p+256][k])
                                         // where W = concat_k(Wih, Whh), k in [0,256)

struct LstmParams {
    const float* Wih[4];
    const float* Whh[4];
    const float* bias[4];
};
struct ConvParams {
    const float* w[4];
    const float* b[4];
};

// --------------------------------------------------------------------------
// Packed f32x2 helpers (Blackwell FFMA2 — only reachable via PTX).
// --------------------------------------------------------------------------
__device__ __forceinline__ ull dup2(float w) {
    ull r; asm("mov.b64 %0, {%1, %1};" : "=l"(r) : "f"(w)); return r;
}
__device__ __forceinline__ void fma2(ull& d, ull a, ull b) {
    asm("fma.rn.f32x2 %0, %1, %2, %0;" : "+l"(d) : "l"(a), "l"(b));
}
__device__ __forceinline__ float2 unpack2(ull a) {
    float2 u; asm("mov.b64 {%0, %1}, %2;" : "=f"(u.x), "=f"(u.y) : "l"(a)); return u;
}

__device__ __forceinline__ float sigf(float x)  { return 1.0f / (1.0f + __expf(-x)); }
__device__ __forceinline__ float tanhf_(float x){ return 2.0f / (1.0f + __expf(-2.0f * x)) - 1.0f; }

// --------------------------------------------------------------------------
// Kernel 0: pack weights into [k][pair] float2 layout (runs every launch,
// deterministic). idx = k*256 + p; pair p covers gates p and p+256.
// --------------------------------------------------------------------------
__global__ __launch_bounds__(256) void pack_weights_kernel(LstmParams P) {
    int lstm = blockIdx.y;
    int idx = blockIdx.x * 256 + threadIdx.x;  // 0..65535
    int k = idx >> 8;
    int p = idx & 255;
    const float* __restrict__ Wih = P.Wih[lstm];
    const float* __restrict__ Whh = P.Whh[lstm];
    float a, b;
    if (k < 128) {
        a = Wih[p * 128 + k];
        b = Wih[(p + 256) * 128 + k];
    } else {
        a = Whh[p * 128 + (k - 128)];
        b = Whh[(p + 256) * 128 + (k - 128)];
    }
    g_Wt[lstm][idx] = make_float2(a, b);
}

// --------------------------------------------------------------------------
// Kernel 1: transpose x[B,C,H,W] into the two [n][t][c] scan layouts.
// --------------------------------------------------------------------------
__global__ __launch_bounds__(256) void transpose_kernel(const float* __restrict__ x) {
    __shared__ float s[128 * 65];
    int b = blockIdx.x >> 6;
    int h = blockIdx.x & 63;
    int tid = threadIdx.x;

    const float* xb = x + (size_t)b * 128 * 4096 + (size_t)h * 64;
    for (int idx = tid; idx < 128 * 64; idx += 256) {
        int c = idx >> 6, w = idx & 63;
        s[c * 65 + w] = xb[(size_t)c * 4096 + w];
    }
    __syncthreads();

    float* xv = g_xT[0] + (size_t)(b * 64 + h) * 64 * 128;
    for (int idx = tid; idx < 128 * 64; idx += 256) {
        int w = idx >> 7, c = idx & 127;
        xv[w * 128 + c] = s[c * 65 + w];
    }
    float* xh = g_xT[1] + (size_t)b * 64 * 64 * 128 + (size_t)h * 128;
    for (int idx = tid; idx < 128 * 64; idx += 256) {
        int w = idx >> 7, c = idx & 127;
        xh[(size_t)w * 64 * 128 + c] = s[c * 65 + w];
    }
}

// --------------------------------------------------------------------------
// Kernel 2: fused LSTM recurrence with packed f32x2 FMA (FFMA2).
// grid = (128 row-blocks, 4 LSTMs), 256 threads. CTA owns 16 rows x 64 steps.
// Per step:
//   stage x_t into sV[k][row] (k in [0,256) = concat(x,h); h fed by combine)
//   GEMM: thread t owns gate pair (t, t+256); 16 f32x2 accumulators cover
//         8 row-pairs x 2 gates: z[(r,r+1)][g] += (v[r][k],v[r+1][k])*dup(W[g][k])
//   combine: thread (ch, rg) owns 8 cells; c-state in regs; h -> sV + gmem.
// Issue budget per SMSP per k: 32 packed-FMA x 2 = 64 cyc (binding);
// 16 LDS.64 (broadcast) = 32, LDG.64 = 8, dup MOVs = 8 hide under it.
// --------------------------------------------------------------------------
__global__ __launch_bounds__(256) void lstm_kernel(LstmParams P) {
    int lstm = blockIdx.y;
    int n0 = blockIdx.x * 16;

    const float2* __restrict__ Wt   = g_Wt[lstm];
    const float*  __restrict__ bias = P.bias[lstm];
    const float*  __restrict__ xT   = g_xT[lstm >> 1];
    float*        __restrict__ Hout = g_H[lstm];
    const bool rev = (lstm & 1) != 0;

    __shared__ float sV[256 * 16];   // [k][row], 16 KB
    __shared__ float sZ[16 * 512];   // [row][gate], 32 KB  (total 49152 B = 48 KB static cap)

    int tid = threadIdx.x;
    int ch = tid & 127;              // combine/stage: channel
    int rg = tid >> 7;               // combine/stage: row group (0/1)
    int r0 = rg * 8;

    ull bias0p = dup2(bias[tid]);
    ull bias1p = dup2(bias[tid + 256]);

    float c[8];
    #pragma unroll
    for (int r = 0; r < 8; r++) c[r] = 0.f;

    // zero h-part of sV (visible after first in-loop barrier)
    #pragma unroll
    for (int r = 0; r < 8; r++) sV[(128 + ch) * 16 + r0 + r] = 0.f;

    for (int tt = 0; tt < 64; ++tt) {
        int t = rev ? 63 - tt : tt;

        // stage x_t into sV[0..128)[rows]; coalesced gmem reads (128 lanes x 4B)
        const float* xsrc = xT + ((size_t)(n0 + r0) * 64 + t) * 128 + ch;
        #pragma unroll
        for (int r = 0; r < 8; r++)
            sV[ch * 16 + r0 + r] = xsrc[(size_t)r * 8192];
        __syncthreads();

        // ---- GEMM: z = bias + [x|h] * W^T, packed over row-pairs ----
        ull a0[8], a1[8];
        #pragma unroll
        for (int rp = 0; rp < 8; rp++) { a0[rp] = bias0p; a1[rp] = bias1p; }

        #pragma unroll 4
        for (int k = 0; k < 256; k++) {
            float2 w = Wt[k * 256 + tid];               // coalesced LDG.64 (L2-resident)
            ull w0 = dup2(w.x), w1 = dup2(w.y);
            const ull* vp = (const ull*)(sV + k * 16);  // uniform address -> broadcast LDS.64
            #pragma unroll
            for (int rp = 0; rp < 8; rp++) {
                ull v = vp[rp];
                fma2(a0[rp], v, w0);
                fma2(a1[rp], v, w1);
            }
        }

        // write z to smem: lane-consecutive gate index -> conflict-free
        #pragma unroll
        for (int rp = 0; rp < 8; rp++) {
            float2 z0 = unpack2(a0[rp]);
            float2 z1 = unpack2(a1[rp]);
            sZ[(2 * rp)     * 512 + tid]       = z0.x;
            sZ[(2 * rp + 1) * 512 + tid]       = z0.y;
            sZ[(2 * rp)     * 512 + tid + 256] = z1.x;
            sZ[(2 * rp + 1) * 512 + tid + 256] = z1.y;
        }
        __syncthreads();

        // ---- gate combine (i, f, g, o) ----
        #pragma unroll
        for (int r = 0; r < 8; r++) {
            int row = r0 + r;
            const float* zr = sZ + row * 512 + ch;
            float zi = zr[0], zf = zr[128], zg = zr[256], zo = zr[384];
            c[r] = sigf(zf) * c[r] + sigf(zi) * tanhf_(zg);
            float h = sigf(zo) * tanhf_(c[r]);
            sV[(128 + ch) * 16 + row] = h;                               // feed next step
            Hout[((size_t)(n0 + row) * 64 + t) * 128 + ch] = h;          // coalesced
        }
        // no extra barrier: h-writes happen-before this thread's next-iteration
        // __syncthreads; next stage touches only the disjoint x-part of sV,
        // and sZ is not written again until after that barrier.
    }
}

// --------------------------------------------------------------------------
// Kernel 3: 1x1 conv. grid = (4096 position tiles, 4 outputs), 256 threads.
// CTA: 32 positions x 128 out-channels; thread: 4x4 register tile.
// --------------------------------------------------------------------------
__global__ __launch_bounds__(256) void conv_kernel(ConvParams P, float* __restrict__ out) {
    int k = blockIdx.y;                                   // 0:down 1:up 2:right 3:left
    int src = (k == 0) ? 1 : ((k == 1) ? 0 : k);          // down<-vb, up<-vf, right<-hf, left<-hb
    const float* __restrict__ Hg   = g_H[src];
    const float* __restrict__ W    = P.w[k];
    const float* __restrict__ bias = P.b[k];
    float* __restrict__ outk = out + (size_t)k * NPLANE;

    __shared__ float Hs[32 * 132];
    int tid = threadIdx.x;
    int p0 = blockIdx.x * 32;

    for (int idx = tid; idx < 32 * 128; idx += 256) {
        int p = idx >> 7, c = idx & 127;
        Hs[p * 132 + c] = Hg[(size_t)(p0 + p) * 128 + c];
    }
    __syncthreads();

    int tp = tid & 7;
    int to = tid >> 3;

    float acc[4][4];
    #pragma unroll
    for (int j = 0; j < 4; j++) {
        float bj = bias[to + 32 * j];
        #pragma unroll
        for (int i = 0; i < 4; i++) acc[i][j] = bj;
    }

    #pragma unroll 4
    for (int k4 = 0; k4 < 32; k4++) {
        float4 wv[4];
        #pragma unroll
        for (int j = 0; j < 4; j++)
            wv[j] = *(const float4*)(W + (size_t)(to + 32 * j) * 128 + k4 * 4);
        #pragma unroll
        for (int i = 0; i < 4; i++) {
            float4 hv = *(const float4*)(Hs + (tp + 8 * i) * 132 + k4 * 4);
            #pragma unroll
            for (int j = 0; j < 4; j++)
                acc[i][j] += hv.x * wv[j].x + hv.y * wv[j].y + hv.z * wv[j].z + hv.w * wv[j].w;
        }
    }

    #pragma unroll
    for (int i = 0; i < 4; i++) {
        int p = p0 + tp + 8 * i;
        int b = p >> 12, q = p & 4095;
        float* ob = outk + (size_t)b * 128 * 4096 + q;
        #pragma unroll
        for (int j = 0; j < 4; j++)
            ob[(size_t)(to + 32 * j) * 4096] = acc[i][j];
    }
}

// --------------------------------------------------------------------------
// Launch. Inputs (metadata order):
// 0:x  1-3:vWih_f,vWhh_f,vb_f  4-6:vWih_b,vWhh_b,vb_b
// 7-9:hWih_f,hWhh_f,hb_f  10-12:hWih_b,hWhh_b,hb_b
// 13..20: (w,b) for down, up, right, left
// --------------------------------------------------------------------------
extern "C" void kernel_launch(void* const* d_in, const int* in_sizes, int n_in,
                              void* d_out, int out_size) {
    (void)in_sizes; (void)n_in; (void)out_size;
    const float* x = (const float*)d_in[0];

    LstmParams LP;
    for (int l = 0; l < 4; l++) {
        LP.Wih[l]  = (const float*)d_in[1 + 3 * l];
        LP.Whh[l]  = (const float*)d_in[2 + 3 * l];
        LP.bias[l] = (const float*)d_in[3 + 3 * l];
    }
    ConvParams CP;
    for (int k = 0; k < 4; k++) {
        CP.w[k] = (const float*)d_in[13 + 2 * k];
        CP.b[k] = (const float*)d_in[14 + 2 * k];
    }

    pack_weights_kernel<<<dim3(256, 4), 256>>>(LP);
    transpose_kernel<<<2048, 256>>>(x);
    lstm_kernel<<<dim3(128, 4), 256>>>(LP);
    conv_kernel<<<dim3(4096, 4), 256>>>(CP, (float*)d_out);
}

// round 9
// speedup vs baseline: 1.9578x; 1.0044x over previous
#include <cuda_runtime.h>
#include <math.h>

// Problem constants: C=128, B=32, H=W=64.
// Per-LSTM: N = 2048 rows, T = 64 steps, C = 128 channels, 4C = 512 gates.
#define NPLANE 16777216  // 2048*64*128

typedef unsigned long long ull;

// Scratch (device globals; no runtime allocation).
__device__ float g_xT[2][NPLANE];        // [0]=vertical [1]=horizontal, layout [n][t][c]
__device__ float g_H[4][NPLANE];         // LSTM hidden outputs {vf, vb, hf, hb}, [n][t][c]
__device__ float2 g_Wt[4][256 * 256];    // packed weights: [lstm][k*256 + p] = (W[p][k], W[p+256][k])
                                         // where W = concat_k(Wih, Whh), k in [0,256)

struct LstmParams {
    const float* Wih[4];
    const float* Whh[4];
    const float* bias[4];
};
struct ConvParams {
    const float* w[4];
    const float* b[4];
};

// --------------------------------------------------------------------------
// Packed f32x2 helpers (Blackwell FFMA2 — only reachable via PTX).
// --------------------------------------------------------------------------
__device__ __forceinline__ ull dup2(float w) {
    ull r; asm("mov.b64 %0, {%1, %1};" : "=l"(r) : "f"(w)); return r;
}
__device__ __forceinline__ void fma2(ull& d, ull a, ull b) {
    asm("fma.rn.f32x2 %0, %1, %2, %0;" : "+l"(d) : "l"(a), "l"(b));
}
__device__ __forceinline__ float2 unpack2(ull a) {
    float2 u; asm("mov.b64 {%0, %1}, %2;" : "=f"(u.x), "=f"(u.y) : "l"(a)); return u;
}

__device__ __forceinline__ float sigf(float x)  { return 1.0f / (1.0f + __expf(-x)); }
__device__ __forceinline__ float tanhf_(float x){ return 2.0f / (1.0f + __expf(-2.0f * x)) - 1.0f; }

// --------------------------------------------------------------------------
// Kernel 0: pack weights into [k][pair] float2 layout (runs every launch,
// deterministic). idx = k*256 + p; pair p covers gates p and p+256.
// --------------------------------------------------------------------------
__global__ __launch_bounds__(256) void pack_weights_kernel(LstmParams P) {
    int lstm = blockIdx.y;
    int idx = blockIdx.x * 256 + threadIdx.x;  // 0..65535
    int k = idx >> 8;
    int p = idx & 255;
    const float* __restrict__ Wih = P.Wih[lstm];
    const float* __restrict__ Whh = P.Whh[lstm];
    float a, b;
    if (k < 128) {
        a = Wih[p * 128 + k];
        b = Wih[(p + 256) * 128 + k];
    } else {
        a = Whh[p * 128 + (k - 128)];
        b = Whh[(p + 256) * 128 + (k - 128)];
    }
    g_Wt[lstm][idx] = make_float2(a, b);
}

// --------------------------------------------------------------------------
// Kernel 1: transpose x[B,C,H,W] into the two [n][t][c] scan layouts.
// --------------------------------------------------------------------------
__global__ __launch_bounds__(256) void transpose_kernel(const float* __restrict__ x) {
    __shared__ float s[128 * 65];
    int b = blockIdx.x >> 6;
    int h = blockIdx.x & 63;
    int tid = threadIdx.x;

    const float* xb = x + (size_t)b * 128 * 4096 + (size_t)h * 64;
    for (int idx = tid; idx < 128 * 64; idx += 256) {
        int c = idx >> 6, w = idx & 63;
        s[c * 65 + w] = xb[(size_t)c * 4096 + w];
    }
    __syncthreads();

    float* xv = g_xT[0] + (size_t)(b * 64 + h) * 64 * 128;
    for (int idx = tid; idx < 128 * 64; idx += 256) {
        int w = idx >> 7, c = idx & 127;
        xv[w * 128 + c] = s[c * 65 + w];
    }
    float* xh = g_xT[1] + (size_t)b * 64 * 64 * 128 + (size_t)h * 128;
    for (int idx = tid; idx < 128 * 64; idx += 256) {
        int w = idx >> 7, c = idx & 127;
        xh[(size_t)w * 64 * 128 + c] = s[c * 65 + w];
    }
}

// --------------------------------------------------------------------------
// Kernel 2: fused LSTM recurrence with packed f32x2 FMA (FFMA2).
// grid = (128 row-blocks, 4 LSTMs), 256 threads. CTA owns 16 rows x 64 steps.
// Per step:
//   stage x_t into sV[k][row] (k in [0,256) = concat(x,h); h fed by combine)
//   GEMM: thread t owns gate pair (t, t+256); 16 f32x2 accumulators cover
//         8 row-pairs x 2 gates: z[(r,r+1)][g] += (v[r][k],v[r+1][k])*dup(W[g][k])
//   combine: thread (ch, rg) owns 8 cells; c-state in regs; h -> sV + gmem.
// Issue budget per SMSP per k: 32 packed-FMA x 2 = 64 cyc (binding);
// 16 LDS.64 (broadcast) = 32, LDG.64 = 8, dup MOVs = 8 hide under it.
// --------------------------------------------------------------------------
__global__ __launch_bounds__(256) void lstm_kernel(LstmParams P) {
    int lstm = blockIdx.y;
    int n0 = blockIdx.x * 16;

    const float2* __restrict__ Wt   = g_Wt[lstm];
    const float*  __restrict__ bias = P.bias[lstm];
    const float*  __restrict__ xT   = g_xT[lstm >> 1];
    float*        __restrict__ Hout = g_H[lstm];
    const bool rev = (lstm & 1) != 0;

    __shared__ float sV[256 * 16];   // [k][row], 16 KB
    __shared__ float sZ[16 * 512];   // [row][gate], 32 KB  (total 49152 B = 48 KB static cap)

    int tid = threadIdx.x;
    int ch = tid & 127;              // combine/stage: channel
    int rg = tid >> 7;               // combine/stage: row group (0/1)
    int r0 = rg * 8;

    ull bias0p = dup2(bias[tid]);
    ull bias1p = dup2(bias[tid + 256]);

    float c[8];
    #pragma unroll
    for (int r = 0; r < 8; r++) c[r] = 0.f;

    // zero h-part of sV (visible after first in-loop barrier)
    #pragma unroll
    for (int r = 0; r < 8; r++) sV[(128 + ch) * 16 + r0 + r] = 0.f;

    for (int tt = 0; tt < 64; ++tt) {
        int t = rev ? 63 - tt : tt;

        // stage x_t into sV[0..128)[rows]; coalesced gmem reads (128 lanes x 4B)
        const float* xsrc = xT + ((size_t)(n0 + r0) * 64 + t) * 128 + ch;
        #pragma unroll
        for (int r = 0; r < 8; r++)
            sV[ch * 16 + r0 + r] = xsrc[(size_t)r * 8192];
        __syncthreads();

        // ---- GEMM: z = bias + [x|h] * W^T, packed over row-pairs ----
        ull a0[8], a1[8];
        #pragma unroll
        for (int rp = 0; rp < 8; rp++) { a0[rp] = bias0p; a1[rp] = bias1p; }

        #pragma unroll 4
        for (int k = 0; k < 256; k++) {
            float2 w = Wt[k * 256 + tid];               // coalesced LDG.64 (L2-resident)
            ull w0 = dup2(w.x), w1 = dup2(w.y);
            const ull* vp = (const ull*)(sV + k * 16);  // uniform address -> broadcast LDS.64
            #pragma unroll
            for (int rp = 0; rp < 8; rp++) {
                ull v = vp[rp];
                fma2(a0[rp], v, w0);
                fma2(a1[rp], v, w1);
            }
        }

        // write z to smem: lane-consecutive gate index -> conflict-free
        #pragma unroll
        for (int rp = 0; rp < 8; rp++) {
            float2 z0 = unpack2(a0[rp]);
            float2 z1 = unpack2(a1[rp]);
            sZ[(2 * rp)     * 512 + tid]       = z0.x;
            sZ[(2 * rp + 1) * 512 + tid]       = z0.y;
            sZ[(2 * rp)     * 512 + tid + 256] = z1.x;
            sZ[(2 * rp + 1) * 512 + tid + 256] = z1.y;
        }
        __syncthreads();

        // ---- gate combine (i, f, g, o) ----
        #pragma unroll
        for (int r = 0; r < 8; r++) {
            int row = r0 + r;
            const float* zr = sZ + row * 512 + ch;
            float zi = zr[0], zf = zr[128], zg = zr[256], zo = zr[384];
            c[r] = sigf(zf) * c[r] + sigf(zi) * tanhf_(zg);
            float h = sigf(zo) * tanhf_(c[r]);
            sV[(128 + ch) * 16 + row] = h;                               // feed next step
            Hout[((size_t)(n0 + row) * 64 + t) * 128 + ch] = h;          // coalesced
        }
        // no extra barrier: h-writes happen-before this thread's next-iteration
        // __syncthreads; next stage touches only the disjoint x-part of sV,
        // and sZ is not written again until after that barrier.
    }
}

// --------------------------------------------------------------------------
// Kernel 3: 1x1 conv. grid = (4096 position tiles, 4 outputs), 256 threads.
// CTA: 32 positions x 128 out-channels; thread: 4x4 register tile.
// --------------------------------------------------------------------------
__global__ __launch_bounds__(256) void conv_kernel(ConvParams P, float* __restrict__ out) {
    int k = blockIdx.y;                                   // 0:down 1:up 2:right 3:left
    int src = (k == 0) ? 1 : ((k == 1) ? 0 : k);          // down<-vb, up<-vf, right<-hf, left<-hb
    const float* __restrict__ Hg   = g_H[src];
    const float* __restrict__ W    = P.w[k];
    const float* __restrict__ bias = P.b[k];
    float* __restrict__ outk = out + (size_t)k * NPLANE;

    __shared__ float Hs[32 * 132];
    int tid = threadIdx.x;
    int p0 = blockIdx.x * 32;

    for (int idx = tid; idx < 32 * 128; idx += 256) {
        int p = idx >> 7, c = idx & 127;
        Hs[p * 132 + c] = Hg[(size_t)(p0 + p) * 128 + c];
    }
    __syncthreads();

    int tp = tid & 7;
    int to = tid >> 3;

    float acc[4][4];
    #pragma unroll
    for (int j = 0; j < 4; j++) {
        float bj = bias[to + 32 * j];
        #pragma unroll
        for (int i = 0; i < 4; i++) acc[i][j] = bj;
    }

    #pragma unroll 4
    for (int k4 = 0; k4 < 32; k4++) {
        float4 wv[4];
        #pragma unroll
        for (int j = 0; j < 4; j++)
            wv[j] = *(const float4*)(W + (size_t)(to + 32 * j) * 128 + k4 * 4);
        #pragma unroll
        for (int i = 0; i < 4; i++) {
            float4 hv = *(const float4*)(Hs + (tp + 8 * i) * 132 + k4 * 4);
            #pragma unroll
            for (int j = 0; j < 4; j++)
                acc[i][j] += hv.x * wv[j].x + hv.y * wv[j].y + hv.z * wv[j].z + hv.w * wv[j].w;
        }
    }

    #pragma unroll
    for (int i = 0; i < 4; i++) {
        int p = p0 + tp + 8 * i;
        int b = p >> 12, q = p & 4095;
        float* ob = outk + (size_t)b * 128 * 4096 + q;
        #pragma unroll
        for (int j = 0; j < 4; j++)
            ob[(size_t)(to + 32 * j) * 4096] = acc[i][j];
    }
}

// --------------------------------------------------------------------------
// Launch. Inputs (metadata order):
// 0:x  1-3:vWih_f,vWhh_f,vb_f  4-6:vWih_b,vWhh_b,vb_b
// 7-9:hWih_f,hWhh_f,hb_f  10-12:hWih_b,hWhh_b,hb_b
// 13..20: (w,b) for down, up, right, left
// --------------------------------------------------------------------------
extern "C" void kernel_launch(void* const* d_in, const int* in_sizes, int n_in,
                              void* d_out, int out_size) {
    (void)in_sizes; (void)n_in; (void)out_size;
    const float* x = (const float*)d_in[0];

    LstmParams LP;
    for (int l = 0; l < 4; l++) {
        LP.Wih[l]  = (const float*)d_in[1 + 3 * l];
        LP.Whh[l]  = (const float*)d_in[2 + 3 * l];
        LP.bias[l] = (const float*)d_in[3 + 3 * l];
    }
    ConvParams CP;
    for (int k = 0; k < 4; k++) {
        CP.w[k] = (const float*)d_in[13 + 2 * k];
        CP.b[k] = (const float*)d_in[14 + 2 * k];
    }

    pack_weights_kernel<<<dim3(256, 4), 256>>>(LP);
    transpose_kernel<<<2048, 256>>>(x);
    lstm_kernel<<<dim3(128, 4), 256>>>(LP);
    conv_kernel<<<dim3(4096, 4), 256>>>(CP, (float*)d_out);
}

// round 11
// speedup vs baseline: 2.2826x; 1.1659x over previous
#include <cuda_runtime.h>
#include <math.h>

// Problem constants: C=128, B=32, H=W=64.
// Per-LSTM: N = 2048 rows, T = 64 steps, C = 128 channels, 4C = 512 gates.
#define NPLANE 16777216  // 2048*64*128

typedef unsigned long long ull;

// Scratch (device globals; no runtime allocation).
__device__ float g_xT[2][NPLANE];        // [0]=vertical [1]=horizontal, layout [n][t][c]
__device__ float g_H[4][NPLANE];         // LSTM hidden outputs {vf, vb, hf, hb}, [n][t][c]
__device__ float4 g_W4[4][256 * 128];    // lstm weights: [lstm][k*128+ch] = (Wi,Wf,Wg,Wo)[ch] at col k
                                         // k<128 from Wih, k>=128 from Whh (concat over [x|h])
__device__ float4 g_Wc4[4][128 * 32];    // conv weights: [cv][k*32+to] = W[{to,to+32,to+64,to+96}][k]

struct LstmParams {
    const float* Wih[4];
    const float* Whh[4];
    const float* bias[4];
};
struct ConvParams {
    const float* w[4];
    const float* b[4];
};

// --------------------------------------------------------------------------
// Packed f32x2 helpers (Blackwell FFMA2 — only reachable via PTX).
// --------------------------------------------------------------------------
__device__ __forceinline__ ull dup2(float w) {
    ull r; asm("mov.b64 %0, {%1, %1};" : "=l"(r) : "f"(w)); return r;
}
__device__ __forceinline__ void fma2(ull& d, ull a, ull b) {
    asm("fma.rn.f32x2 %0, %1, %2, %0;" : "+l"(d) : "l"(a), "l"(b));
}
__device__ __forceinline__ float2 unpack2(ull a) {
    float2 u; asm("mov.b64 {%0, %1}, %2;" : "=f"(u.x), "=f"(u.y) : "l"(a)); return u;
}

__device__ __forceinline__ float sigf(float x)  { return 1.0f / (1.0f + __expf(-x)); }
__device__ __forceinline__ float tanhf_(float x){ return 2.0f / (1.0f + __expf(-2.0f * x)) - 1.0f; }

// --------------------------------------------------------------------------
// Kernel 0a: pack LSTM weights into gate-quadruple float4 layout.
// idx = k*128 + ch -> (W[ch][k], W[ch+128][k], W[ch+256][k], W[ch+384][k]).
// --------------------------------------------------------------------------
__global__ __launch_bounds__(256) void pack_lstm_kernel(LstmParams P) {
    int lstm = blockIdx.y;
    int idx = blockIdx.x * 256 + threadIdx.x;   // 0..32767
    int k = idx >> 7;
    int ch = idx & 127;
    const float* __restrict__ W = (k < 128) ? P.Wih[lstm] : P.Whh[lstm];
    int kk = k & 127;
    g_W4[lstm][idx] = make_float4(W[(size_t)ch * 128 + kk],
                                  W[(size_t)(ch + 128) * 128 + kk],
                                  W[(size_t)(ch + 256) * 128 + kk],
                                  W[(size_t)(ch + 384) * 128 + kk]);
}

// Kernel 0b: pack conv weights: [cv][k*32+to] = W[{to,to+32,to+64,to+96}][k]
__global__ __launch_bounds__(256) void pack_conv_kernel(ConvParams P) {
    int cv = blockIdx.y;
    int idx = blockIdx.x * 256 + threadIdx.x;   // 0..4095
    int k = idx >> 5;
    int to = idx & 31;
    const float* __restrict__ W = P.w[cv];
    g_Wc4[cv][idx] = make_float4(W[(size_t)to * 128 + k],
                                 W[(size_t)(to + 32) * 128 + k],
                                 W[(size_t)(to + 64) * 128 + k],
                                 W[(size_t)(to + 96) * 128 + k]);
}

// --------------------------------------------------------------------------
// Kernel 1: transpose x[B,C,H,W] into the two [n][t][c] scan layouts.
// --------------------------------------------------------------------------
__global__ __launch_bounds__(256) void transpose_kernel(const float* __restrict__ x) {
    __shared__ float s[128 * 65];
    int b = blockIdx.x >> 6;
    int h = blockIdx.x & 63;
    int tid = threadIdx.x;

    const float* xb = x + (size_t)b * 128 * 4096 + (size_t)h * 64;
    for (int idx = tid; idx < 128 * 64; idx += 256) {
        int c = idx >> 6, w = idx & 63;
        s[c * 65 + w] = xb[(size_t)c * 4096 + w];
    }
    __syncthreads();

    float* xv = g_xT[0] + (size_t)(b * 64 + h) * 64 * 128;
    for (int idx = tid; idx < 128 * 64; idx += 256) {
        int w = idx >> 7, c = idx & 127;
        xv[w * 128 + c] = s[c * 65 + w];
    }
    float* xh = g_xT[1] + (size_t)b * 64 * 64 * 128 + (size_t)h * 128;
    for (int idx = tid; idx < 128 * 64; idx += 256) {
        int w = idx >> 7, c = idx & 127;
        xh[(size_t)w * 64 * 128 + c] = s[c * 65 + w];
    }
}

// --------------------------------------------------------------------------
// Kernel 2: fused LSTM recurrence, gate-local combine, FFMA2.
// grid = (128 row-blocks, 4 LSTMs), 256 threads. CTA owns 16 rows x 64 steps.
// Thread (ch = tid&127, rg = tid>>7): owns the FULL gate quadruple (i,f,g,o)
// of channel ch for rows rg*8 .. rg*8+7 (4 row-pairs). 16 f32x2 accumulators.
// z never leaves registers -> no z-exchange smem, no second barrier.
// sV[k][row] double-buffered (x|h concat, k in [0,256)): 1 barrier/step.
// Per-k issue budget/warp: 16 FMA2 (binding, 32 fma-cyc) + 4 LDS.64(bcast)
// + 1 LDG.128 + 4 dup-MOV ~= 26 issues -> 81% slot pressure.
// --------------------------------------------------------------------------
__global__ __launch_bounds__(256) void lstm_kernel(LstmParams P) {
    int lstm = blockIdx.y;
    int n0 = blockIdx.x * 16;

    const float4* __restrict__ W4   = g_W4[lstm];
    const float*  __restrict__ bias = P.bias[lstm];
    const float*  __restrict__ xT   = g_xT[lstm >> 1];
    float*        __restrict__ Hout = g_H[lstm];
    const bool rev = (lstm & 1) != 0;

    __shared__ float sV[2][256 * 16];   // [buf][k][row], 32 KB total

    int tid = threadIdx.x;
    int ch = tid & 127;
    int rg = tid >> 7;
    int r0 = rg * 8;

    ull bi = dup2(bias[ch]);
    ull bf = dup2(bias[ch + 128]);
    ull bg = dup2(bias[ch + 256]);
    ull bo = dup2(bias[ch + 384]);

    float c[8];
    #pragma unroll
    for (int r = 0; r < 8; r++) c[r] = 0.f;

    // zero h-part of buffer 0 (read as h[-1] by step 0)
    #pragma unroll
    for (int r = 0; r < 8; r++) sV[0][(128 + ch) * 16 + r0 + r] = 0.f;

    for (int tt = 0; tt < 64; ++tt) {
        int t = rev ? 63 - tt : tt;
        int buf = tt & 1;
        float* __restrict__ Vb = sV[buf];

        // stage x_t into Vb x-part; coalesced gmem reads (128 lanes x 4B)
        const float* xsrc = xT + ((size_t)(n0 + r0) * 64 + t) * 128 + ch;
        #pragma unroll
        for (int r = 0; r < 8; r++)
            Vb[ch * 16 + r0 + r] = xsrc[(size_t)r * 8192];
        __syncthreads();   // x[t] staged AND h[t-1] (written pre-barrier) visible

        // ---- GEMM: z = bias + [x|h] * W^T ; accs [gate][rowpair] ----
        ull ai[4], af[4], ag[4], ao[4];
        #pragma unroll
        for (int rp = 0; rp < 4; rp++) { ai[rp] = bi; af[rp] = bf; ag[rp] = bg; ao[rp] = bo; }

        const ull* __restrict__ Vp = (const ull*)Vb + rg * 4;
        #pragma unroll 4
        for (int k = 0; k < 256; k++) {
            float4 w = W4[k * 128 + ch];            // coalesced LDG.128 (L1/L2-resident)
            ull wi = dup2(w.x), wf = dup2(w.y), wg = dup2(w.z), wo = dup2(w.w);
            #pragma unroll
            for (int rp = 0; rp < 4; rp++) {
                ull v = Vp[k * 8 + rp];             // broadcast LDS.64 (row-pair)
                fma2(ai[rp], v, wi);
                fma2(af[rp], v, wf);
                fma2(ag[rp], v, wg);
                fma2(ao[rp], v, wo);
            }
        }

        // ---- gate combine, fully local ----
        float* __restrict__ Vn = sV[buf ^ 1];       // h[t] feeds next step's buffer
        #pragma unroll
        for (int rp = 0; rp < 4; rp++) {
            float2 zi = unpack2(ai[rp]);
            float2 zf = unpack2(af[rp]);
            float2 zg = unpack2(ag[rp]);
            float2 zo = unpack2(ao[rp]);

            int row = r0 + 2 * rp;
            c[2 * rp]     = sigf(zf.x) * c[2 * rp]     + sigf(zi.x) * tanhf_(zg.x);
            c[2 * rp + 1] = sigf(zf.y) * c[2 * rp + 1] + sigf(zi.y) * tanhf_(zg.y);
            float h0 = sigf(zo.x) * tanhf_(c[2 * rp]);
            float h1 = sigf(zo.y) * tanhf_(c[2 * rp + 1]);

            Vn[(128 + ch) * 16 + row]     = h0;
            Vn[(128 + ch) * 16 + row + 1] = h1;
            Hout[((size_t)(n0 + row) * 64 + t) * 128 + ch]     = h0;   // coalesced
            Hout[((size_t)(n0 + row + 1) * 64 + t) * 128 + ch] = h1;
        }
        // next iteration's stage writes the OTHER buffer's x-part and the
        // barrier there orders these h-writes before all GEMM reads.
    }
}

// --------------------------------------------------------------------------
// Kernel 3: 1x1 conv with FFMA2. grid = (4096 tiles, 4 outputs), 128 threads.
// CTA: 32 positions x 128 outs. Thread: 4 outs x 4 position-pairs (16 f32x2).
// Hs stored transposed [c][pos] (pad 34) so a position-pair is one LDS.64.
// --------------------------------------------------------------------------
__global__ __launch_bounds__(128) void conv_kernel(ConvParams P, float* __restrict__ out) {
    int kk = blockIdx.y;                                  // 0:down 1:up 2:right 3:left
    int src = (kk == 0) ? 1 : ((kk == 1) ? 0 : kk);       // down<-vb, up<-vf, right<-hf, left<-hb
    const float*  __restrict__ Hg   = g_H[src];
    const float4* __restrict__ W4   = g_Wc4[kk];
    const float*  __restrict__ bias = P.b[kk];
    float* __restrict__ outk = out + (size_t)kk * NPLANE;

    __shared__ float Hs[128 * 34];                        // [c][pos], pad 34
    int tid = threadIdx.x;
    int p0 = blockIdx.x * 32;

    for (int idx = tid; idx < 32 * 128; idx += 128) {
        int p = idx >> 7, c = idx & 127;                  // coalesced gmem read
        Hs[c * 34 + p] = Hg[(size_t)(p0 + p) * 128 + c];
    }
    __syncthreads();

    int tp = tid & 3;    // pair base: pairs {tp, tp+4, tp+8, tp+12}
    int to = tid >> 2;   // outs: {to, to+32, to+64, to+96}

    ull acc[4][4];       // [out][pair]
    {
        ull b0 = dup2(bias[to]);
        ull b1 = dup2(bias[to + 32]);
        ull b2 = dup2(bias[to + 64]);
        ull b3 = dup2(bias[to + 96]);
        #pragma unroll
        for (int i = 0; i < 4; i++) { acc[0][i] = b0; acc[1][i] = b1; acc[2][i] = b2; acc[3][i] = b3; }
    }

    #pragma unroll 4
    for (int k = 0; k < 128; k++) {
        float4 w = W4[k * 32 + to];
        ull w0 = dup2(w.x), w1 = dup2(w.y), w2 = dup2(w.z), w3 = dup2(w.w);
        const ull* hp = (const ull*)(Hs + k * 34) + tp;
        #pragma unroll
        for (int i = 0; i < 4; i++) {
            ull v = hp[i * 4];
            fma2(acc[0][i], v, w0);
            fma2(acc[1][i], v, w1);
            fma2(acc[2][i], v, w2);
            fma2(acc[3][i], v, w3);
        }
    }

    #pragma unroll
    for (int i = 0; i < 4; i++) {
        int p = p0 + 2 * (tp + 4 * i);
        int b = p >> 12, q = p & 4095;
        float* ob = outk + (size_t)b * 128 * 4096 + q;
        #pragma unroll
        for (int j = 0; j < 4; j++) {
            float2 z = unpack2(acc[j][i]);
            *(float2*)(ob + (size_t)(to + 32 * j) * 4096) = z;   // STG.64, 8B-aligned
        }
    }
}

// --------------------------------------------------------------------------
// Launch. Inputs (metadata order):
// 0:x  1-3:vWih_f,vWhh_f,vb_f  4-6:vWih_b,vWhh_b,vb_b
// 7-9:hWih_f,hWhh_f,hb_f  10-12:hWih_b,hWhh_b,hb_b
// 13..20: (w,b) for down, up, right, left
// --------------------------------------------------------------------------
extern "C" void kernel_launch(void* const* d_in, const int* in_sizes, int n_in,
                              void* d_out, int out_size) {
    (void)in_sizes; (void)n_in; (void)out_size;
    const float* x = (const float*)d_in[0];

    LstmParams LP;
    for (int l = 0; l < 4; l++) {
        LP.Wih[l]  = (const float*)d_in[1 + 3 * l];
        LP.Whh[l]  = (const float*)d_in[2 + 3 * l];
        LP.bias[l] = (const float*)d_in[3 + 3 * l];
    }
    ConvParams CP;
    for (int k = 0; k < 4; k++) {
        CP.w[k] = (const float*)d_in[13 + 2 * k];
        CP.b[k] = (const float*)d_in[14 + 2 * k];
    }

    pack_lstm_kernel<<<dim3(128, 4), 256>>>(LP);
    pack_conv_kernel<<<dim3(16, 4), 256>>>(CP);
    transpose_kernel<<<2048, 256>>>(x);
    lstm_kernel<<<dim3(128, 4), 256>>>(LP);
    conv_kernel<<<dim3(4096, 4), 128>>>(CP, (float*)d_out);
}

// round 12
// speedup vs baseline: 2.7238x; 1.1933x over previous
#include <cuda_runtime.h>
#include <math.h>

// Problem constants: C=128, B=32, H=W=64.
// Per-LSTM: N = 2048 rows, T = 64 steps, C = 128 channels, 4C = 512 gates.
#define NPLANE 16777216  // 2048*64*128

typedef unsigned long long ull;

// Scratch (device globals; no runtime allocation).
__device__ float g_xT[2][NPLANE];        // [0]=vertical [1]=horizontal, layout [n][t][c]
__device__ float g_H[4][NPLANE];         // LSTM hidden outputs {vf, vb, hf, hb}, [n][t][c]
__device__ float4 g_W4[4][256 * 128];    // lstm weights: [lstm][k*128+ch] = (Wi,Wf,Wg,Wo)[ch] at col k
                                         // k<128 from Wih, k>=128 from Whh (concat over [x|h])
__device__ float4 g_Wc4[4][128 * 32];    // conv weights: [cv][k*32+to] = W[{to,to+32,to+64,to+96}][k]

struct LstmParams {
    const float* Wih[4];
    const float* Whh[4];
    const float* bias[4];
};
struct ConvParams {
    const float* w[4];
    const float* b[4];
};

// --------------------------------------------------------------------------
// Packed f32x2 helpers (Blackwell FFMA2 — only reachable via PTX).
// --------------------------------------------------------------------------
__device__ __forceinline__ ull dup2(float w) {
    ull r; asm("mov.b64 %0, {%1, %1};" : "=l"(r) : "f"(w)); return r;
}
__device__ __forceinline__ void fma2(ull& d, ull a, ull b) {
    asm("fma.rn.f32x2 %0, %1, %2, %0;" : "+l"(d) : "l"(a), "l"(b));
}
__device__ __forceinline__ float2 unpack2(ull a) {
    float2 u; asm("mov.b64 {%0, %1}, %2;" : "=f"(u.x), "=f"(u.y) : "l"(a)); return u;
}

__device__ __forceinline__ float sigf(float x)  { return 1.0f / (1.0f + __expf(-x)); }
__device__ __forceinline__ float tanhf_(float x){ return 2.0f / (1.0f + __expf(-2.0f * x)) - 1.0f; }

// --------------------------------------------------------------------------
// Kernel 0a: pack LSTM weights into gate-quadruple float4 layout.
// idx = k*128 + ch -> (W[ch][k], W[ch+128][k], W[ch+256][k], W[ch+384][k]).
// --------------------------------------------------------------------------
__global__ __launch_bounds__(256) void pack_lstm_kernel(LstmParams P) {
    int lstm = blockIdx.y;
    int idx = blockIdx.x * 256 + threadIdx.x;   // 0..32767
    int k = idx >> 7;
    int ch = idx & 127;
    const float* __restrict__ W = (k < 128) ? P.Wih[lstm] : P.Whh[lstm];
    int kk = k & 127;
    g_W4[lstm][idx] = make_float4(W[(size_t)ch * 128 + kk],
                                  W[(size_t)(ch + 128) * 128 + kk],
                                  W[(size_t)(ch + 256) * 128 + kk],
                                  W[(size_t)(ch + 384) * 128 + kk]);
}

// Kernel 0b: pack conv weights: [cv][k*32+to] = W[{to,to+32,to+64,to+96}][k]
__global__ __launch_bounds__(256) void pack_conv_kernel(ConvParams P) {
    int cv = blockIdx.y;
    int idx = blockIdx.x * 256 + threadIdx.x;   // 0..4095
    int k = idx >> 5;
    int to = idx & 31;
    const float* __restrict__ W = P.w[cv];
    g_Wc4[cv][idx] = make_float4(W[(size_t)to * 128 + k],
                                 W[(size_t)(to + 32) * 128 + k],
                                 W[(size_t)(to + 64) * 128 + k],
                                 W[(size_t)(to + 96) * 128 + k]);
}

// --------------------------------------------------------------------------
// Kernel 1: transpose x[B,C,H,W] into the two [n][t][c] scan layouts.
// --------------------------------------------------------------------------
__global__ __launch_bounds__(256) void transpose_kernel(const float* __restrict__ x) {
    __shared__ float s[128 * 65];
    int b = blockIdx.x >> 6;
    int h = blockIdx.x & 63;
    int tid = threadIdx.x;

    const float* xb = x + (size_t)b * 128 * 4096 + (size_t)h * 64;
    for (int idx = tid; idx < 128 * 64; idx += 256) {
        int c = idx >> 6, w = idx & 63;
        s[c * 65 + w] = xb[(size_t)c * 4096 + w];
    }
    __syncthreads();

    float* xv = g_xT[0] + (size_t)(b * 64 + h) * 64 * 128;
    for (int idx = tid; idx < 128 * 64; idx += 256) {
        int w = idx >> 7, c = idx & 127;
        xv[w * 128 + c] = s[c * 65 + w];
    }
    float* xh = g_xT[1] + (size_t)b * 64 * 64 * 128 + (size_t)h * 128;
    for (int idx = tid; idx < 128 * 64; idx += 256) {
        int w = idx >> 7, c = idx & 127;
        xh[(size_t)w * 64 * 128 + c] = s[c * 65 + w];
    }
}

// --------------------------------------------------------------------------
// Kernel 2: fused LSTM recurrence, gate-local combine, FFMA2.
// grid = (64 row-blocks, 4 LSTMs) = 256 CTAs -> SINGLE WAVE at 2 CTAs/SM.
// 512 threads; CTA owns 32 rows x 64 steps.
// Thread (ch = tid&127, rg = tid>>7 in 0..3): gate quadruple (i,f,g,o) of
// channel ch for rows rg*8..rg*8+7 (4 row-pairs, 16 f32x2 accumulators).
// smem: sX [k<128][row] single-buffered (16 KB) + sH [buf][k][row] double-
// buffered (32 KB) = 48 KB static exactly. Two barriers per step.
// Per-k issue/SMSP (8 warps): 8*(16 FMA2 + 4 LDS.64 bcast + 4 MOV + 1 LDG.128)
// ~= 216 issues vs 256 FMA-pipe cycles -> FMA-bound.
// --------------------------------------------------------------------------
__global__ __launch_bounds__(512, 2) void lstm_kernel(LstmParams P) {
    int lstm = blockIdx.y;
    int n0 = blockIdx.x * 32;

    const float4* __restrict__ W4   = g_W4[lstm];
    const float*  __restrict__ bias = P.bias[lstm];
    const float*  __restrict__ xT   = g_xT[lstm >> 1];
    float*        __restrict__ Hout = g_H[lstm];
    const bool rev = (lstm & 1) != 0;

    __shared__ float sX[128 * 32];      // [k][row], x-part, 16 KB
    __shared__ float sH[2][128 * 32];   // [buf][k][row], h-part, 32 KB

    int tid = threadIdx.x;
    int ch = tid & 127;
    int rg = tid >> 7;          // 0..3
    int r0 = rg * 8;

    float bi_f = bias[ch];
    float bf_f = bias[ch + 128];
    float bg_f = bias[ch + 256];
    float bo_f = bias[ch + 384];

    float c[8];
    #pragma unroll
    for (int r = 0; r < 8; r++) c[r] = 0.f;

    // zero h buffer 0 (read as h[-1] by step 0; visible after first barrier)
    #pragma unroll
    for (int r = 0; r < 8; r++) sH[0][ch * 32 + r0 + r] = 0.f;

    for (int tt = 0; tt < 64; ++tt) {
        int t = rev ? 63 - tt : tt;
        int buf = tt & 1;

        // stage x_t; coalesced gmem reads (128 consecutive ch lanes)
        const float* xsrc = xT + ((size_t)(n0 + r0) * 64 + t) * 128 + ch;
        #pragma unroll
        for (int r = 0; r < 8; r++)
            sX[ch * 32 + r0 + r] = xsrc[(size_t)r * 8192];
        __syncthreads();   // x[t] staged AND h[t-1] (pre-barrier writes) visible

        // ---- GEMM: z = bias + x*Wih^T + h*Whh^T ; accs [gate][rowpair] ----
        ull ai[4], af[4], ag[4], ao[4];
        {
            ull bi = dup2(bi_f), bf = dup2(bf_f), bg = dup2(bg_f), bo = dup2(bo_f);
            #pragma unroll
            for (int rp = 0; rp < 4; rp++) { ai[rp] = bi; af[rp] = bf; ag[rp] = bg; ao[rp] = bo; }
        }

        const ull* __restrict__ Xp = (const ull*)sX + rg * 4;
        #pragma unroll 4
        for (int k = 0; k < 128; k++) {
            float4 w = W4[k * 128 + ch];            // coalesced LDG.128 (L1-resident)
            ull wi = dup2(w.x), wf = dup2(w.y), wg = dup2(w.z), wo = dup2(w.w);
            #pragma unroll
            for (int rp = 0; rp < 4; rp++) {
                ull v = Xp[k * 16 + rp];            // broadcast LDS.64 (row-pair)
                fma2(ai[rp], v, wi);
                fma2(af[rp], v, wf);
                fma2(ag[rp], v, wg);
                fma2(ao[rp], v, wo);
            }
        }
        const ull* __restrict__ Hp = (const ull*)sH[buf] + rg * 4;
        #pragma unroll 4
        for (int k = 0; k < 128; k++) {
            float4 w = W4[(k + 128) * 128 + ch];
            ull wi = dup2(w.x), wf = dup2(w.y), wg = dup2(w.z), wo = dup2(w.w);
            #pragma unroll
            for (int rp = 0; rp < 4; rp++) {
                ull v = Hp[k * 16 + rp];
                fma2(ai[rp], v, wi);
                fma2(af[rp], v, wf);
                fma2(ag[rp], v, wg);
                fma2(ao[rp], v, wo);
            }
        }

        // ---- gate combine, fully local; h[t] -> other h buffer + gmem ----
        float* __restrict__ Hn = sH[buf ^ 1];
        #pragma unroll
        for (int rp = 0; rp < 4; rp++) {
            float2 zi = unpack2(ai[rp]);
            float2 zf = unpack2(af[rp]);
            float2 zg = unpack2(ag[rp]);
            float2 zo = unpack2(ao[rp]);

            int row = r0 + 2 * rp;
            c[2 * rp]     = sigf(zf.x) * c[2 * rp]     + sigf(zi.x) * tanhf_(zg.x);
            c[2 * rp + 1] = sigf(zf.y) * c[2 * rp + 1] + sigf(zi.y) * tanhf_(zg.y);
            float h0 = sigf(zo.x) * tanhf_(c[2 * rp]);
            float h1 = sigf(zo.y) * tanhf_(c[2 * rp + 1]);

            Hn[ch * 32 + row]     = h0;
            Hn[ch * 32 + row + 1] = h1;
            Hout[((size_t)(n0 + row) * 64 + t) * 128 + ch]     = h0;   // coalesced
            Hout[((size_t)(n0 + row + 1) * 64 + t) * 128 + ch] = h1;
        }
        __syncthreads();   // all GEMM reads of sX/sH[buf] done before next stage;
                           // h[t] writes ordered before next step's GEMM reads
    }
}

// --------------------------------------------------------------------------
// Kernel 3: 1x1 conv with FFMA2. grid = (4096 tiles, 4 outputs), 128 threads.
// CTA: 32 positions x 128 outs. Thread: 4 outs x 4 position-pairs (16 f32x2).
// Hs stored transposed [c][pos] (pad 34) so a position-pair is one LDS.64.
// --------------------------------------------------------------------------
__global__ __launch_bounds__(128) void conv_kernel(ConvParams P, float* __restrict__ out) {
    int kk = blockIdx.y;                                  // 0:down 1:up 2:right 3:left
    int src = (kk == 0) ? 1 : ((kk == 1) ? 0 : kk);       // down<-vb, up<-vf, right<-hf, left<-hb
    const float*  __restrict__ Hg   = g_H[src];
    const float4* __restrict__ W4   = g_Wc4[kk];
    const float*  __restrict__ bias = P.b[kk];
    float* __restrict__ outk = out + (size_t)kk * NPLANE;

    __shared__ float Hs[128 * 34];                        // [c][pos], pad 34
    int tid = threadIdx.x;
    int p0 = blockIdx.x * 32;

    for (int idx = tid; idx < 32 * 128; idx += 128) {
        int p = idx >> 7, c = idx & 127;                  // coalesced gmem read
        Hs[c * 34 + p] = Hg[(size_t)(p0 + p) * 128 + c];
    }
    __syncthreads();

    int tp = tid & 3;    // pair base: pairs {tp, tp+4, tp+8, tp+12}
    int to = tid >> 2;   // outs: {to, to+32, to+64, to+96}

    ull acc[4][4];       // [out][pair]
    {
        ull b0 = dup2(bias[to]);
        ull b1 = dup2(bias[to + 32]);
        ull b2 = dup2(bias[to + 64]);
        ull b3 = dup2(bias[to + 96]);
        #pragma unroll
        for (int i = 0; i < 4; i++) { acc[0][i] = b0; acc[1][i] = b1; acc[2][i] = b2; acc[3][i] = b3; }
    }

    #pragma unroll 4
    for (int k = 0; k < 128; k++) {
        float4 w = W4[k * 32 + to];
        ull w0 = dup2(w.x), w1 = dup2(w.y), w2 = dup2(w.z), w3 = dup2(w.w);
        const ull* hp = (const ull*)(Hs + k * 34) + tp;
        #pragma unroll
        for (int i = 0; i < 4; i++) {
            ull v = hp[i * 4];
            fma2(acc[0][i], v, w0);
            fma2(acc[1][i], v, w1);
            fma2(acc[2][i], v, w2);
            fma2(acc[3][i], v, w3);
        }
    }

    #pragma unroll
    for (int i = 0; i < 4; i++) {
        int p = p0 + 2 * (tp + 4 * i);
        int b = p >> 12, q = p & 4095;
        float* ob = outk + (size_t)b * 128 * 4096 + q;
        #pragma unroll
        for (int j = 0; j < 4; j++) {
            float2 z = unpack2(acc[j][i]);
            *(float2*)(ob + (size_t)(to + 32 * j) * 4096) = z;   // STG.64, 8B-aligned
        }
    }
}

// --------------------------------------------------------------------------
// Launch. Inputs (metadata order):
// 0:x  1-3:vWih_f,vWhh_f,vb_f  4-6:vWih_b,vWhh_b,vb_b
// 7-9:hWih_f,hWhh_f,hb_f  10-12:hWih_b,hWhh_b,hb_b
// 13..20: (w,b) for down, up, right, left
// --------------------------------------------------------------------------
extern "C" void kernel_launch(void* const* d_in, const int* in_sizes, int n_in,
                              void* d_out, int out_size) {
    (void)in_sizes; (void)n_in; (void)out_size;
    const float* x = (const float*)d_in[0];

    LstmParams LP;
    for (int l = 0; l < 4; l++) {
        LP.Wih[l]  = (const float*)d_in[1 + 3 * l];
        LP.Whh[l]  = (const float*)d_in[2 + 3 * l];
        LP.bias[l] = (const float*)d_in[3 + 3 * l];
    }
    ConvParams CP;
    for (int k = 0; k < 4; k++) {
        CP.w[k] = (const float*)d_in[13 + 2 * k];
        CP.b[k] = (const float*)d_in[14 + 2 * k];
    }

    pack_lstm_kernel<<<dim3(128, 4), 256>>>(LP);
    pack_conv_kernel<<<dim3(16, 4), 256>>>(CP);
    transpose_kernel<<<2048, 256>>>(x);
    lstm_kernel<<<dim3(64, 4), 512>>>(LP);
    conv_kernel<<<dim3(4096, 4), 128>>>(CP, (float*)d_out);
}

// round 13
// speedup vs baseline: 3.0291x; 1.1121x over previous
#include <cuda_runtime.h>
#include <math.h>

// Problem constants: C=128, B=32, H=W=64.
// Per-LSTM: N = 2048 rows, T = 64 steps, C = 128 channels, 4C = 512 gates.
#define NPLANE 16777216  // 2048*64*128

typedef unsigned long long ull;

// Scratch (device globals; no runtime allocation).
__device__ float g_xT[2][NPLANE];        // [0]=vertical [1]=horizontal, layout [n][t][c]
__device__ float g_H[4][NPLANE];         // LSTM hidden outputs {vf, vb, hf, hb}, [n][t][c]
__device__ float4 g_W4[4][256 * 128];    // lstm weights: [lstm][k*128+ch] = (Wi,Wf,Wg,Wo)[ch] at col k
                                         // k<128 from Wih, k>=128 from Whh (concat over [x|h])
__device__ float4 g_Wc4[4][128 * 32];    // conv weights: [cv][k*32+to] = W[{to,to+32,to+64,to+96}][k]

struct LstmParams {
    const float* Wih[4];
    const float* Whh[4];
    const float* bias[4];
};
struct ConvParams {
    const float* w[4];
    const float* b[4];
};

// --------------------------------------------------------------------------
// Packed f32x2 helpers (Blackwell FFMA2 — only reachable via PTX) + cp.async.
// --------------------------------------------------------------------------
__device__ __forceinline__ ull dup2(float w) {
    ull r; asm("mov.b64 %0, {%1, %1};" : "=l"(r) : "f"(w)); return r;
}
__device__ __forceinline__ void fma2(ull& d, ull a, ull b) {
    asm("fma.rn.f32x2 %0, %1, %2, %0;" : "+l"(d) : "l"(a), "l"(b));
}
__device__ __forceinline__ float2 unpack2(ull a) {
    float2 u; asm("mov.b64 {%0, %1}, %2;" : "=f"(u.x), "=f"(u.y) : "l"(a)); return u;
}
__device__ __forceinline__ unsigned smem_u32(const void* p) {
    unsigned a;
    asm("{ .reg .u64 t; cvta.to.shared.u64 t, %1; cvt.u32.u64 %0, t; }" : "=r"(a) : "l"(p));
    return a;
}
__device__ __forceinline__ void cp16(unsigned dst, const void* src) {
    asm volatile("cp.async.cg.shared.global [%0], [%1], 16;" :: "r"(dst), "l"(src));
}
#define CP_COMMIT() asm volatile("cp.async.commit_group;" ::: "memory")
#define CP_WAIT0()  asm volatile("cp.async.wait_group 0;" ::: "memory")

__device__ __forceinline__ float sigf(float x)  { return 1.0f / (1.0f + __expf(-x)); }
__device__ __forceinline__ float tanhf_(float x){ return 2.0f / (1.0f + __expf(-2.0f * x)) - 1.0f; }

// --------------------------------------------------------------------------
// Kernel 0a: pack LSTM weights into gate-quadruple float4 layout.
// idx = k*128 + ch -> (W[ch][k], W[ch+128][k], W[ch+256][k], W[ch+384][k]).
// --------------------------------------------------------------------------
__global__ __launch_bounds__(256) void pack_lstm_kernel(LstmParams P) {
    int lstm = blockIdx.y;
    int idx = blockIdx.x * 256 + threadIdx.x;   // 0..32767
    int k = idx >> 7;
    int ch = idx & 127;
    const float* __restrict__ W = (k < 128) ? P.Wih[lstm] : P.Whh[lstm];
    int kk = k & 127;
    g_W4[lstm][idx] = make_float4(W[(size_t)ch * 128 + kk],
                                  W[(size_t)(ch + 128) * 128 + kk],
                                  W[(size_t)(ch + 256) * 128 + kk],
                                  W[(size_t)(ch + 384) * 128 + kk]);
}

// Kernel 0b: pack conv weights: [cv][k*32+to] = W[{to,to+32,to+64,to+96}][k]
__global__ __launch_bounds__(256) void pack_conv_kernel(ConvParams P) {
    int cv = blockIdx.y;
    int idx = blockIdx.x * 256 + threadIdx.x;   // 0..4095
    int k = idx >> 5;
    int to = idx & 31;
    const float* __restrict__ W = P.w[cv];
    g_Wc4[cv][idx] = make_float4(W[(size_t)to * 128 + k],
                                 W[(size_t)(to + 32) * 128 + k],
                                 W[(size_t)(to + 64) * 128 + k],
                                 W[(size_t)(to + 96) * 128 + k]);
}

// --------------------------------------------------------------------------
// Kernel 1: transpose x[B,C,H,W] into the two [n][t][c] scan layouts.
// --------------------------------------------------------------------------
__global__ __launch_bounds__(256) void transpose_kernel(const float* __restrict__ x) {
    __shared__ float s[128 * 65];
    int b = blockIdx.x >> 6;
    int h = blockIdx.x & 63;
    int tid = threadIdx.x;

    const float* xb = x + (size_t)b * 128 * 4096 + (size_t)h * 64;
    for (int idx = tid; idx < 128 * 64; idx += 256) {
        int c = idx >> 6, w = idx & 63;
        s[c * 65 + w] = xb[(size_t)c * 4096 + w];
    }
    __syncthreads();

    float* xv = g_xT[0] + (size_t)(b * 64 + h) * 64 * 128;
    for (int idx = tid; idx < 128 * 64; idx += 256) {
        int w = idx >> 7, c = idx & 127;
        xv[w * 128 + c] = s[c * 65 + w];
    }
    float* xh = g_xT[1] + (size_t)b * 64 * 64 * 128 + (size_t)h * 128;
    for (int idx = tid; idx < 128 * 64; idx += 256) {
        int w = idx >> 7, c = idx & 127;
        xh[(size_t)w * 64 * 128 + c] = s[c * 65 + w];
    }
}

// --------------------------------------------------------------------------
// Kernel 2: fused LSTM recurrence, FFMA2 + cp.async weight pipeline.
// grid = (64 row-blocks, 4 LSTMs) = 256 CTAs, 512 thr, 2 CTAs/SM, ONE wave.
// CTA owns 32 rows x 64 steps. Thread (ch=tid&127, rg=tid>>7): gate quad
// (i,f,g,o) of channel ch for rows rg*8..rg*8+7 (4 row-pairs, 16 f32x2 accs).
// Weights stream via cp.async in 32 chunks of 8 k (16 KB), double-buffered:
// chunk c+1 flies while chunk c computes from smem -> no LDG scoreboard
// stalls in the GEMM. One wait+barrier per chunk.
// Dynamic smem 80 KB: sX 16K [k<128][row] + sH 2x16K [buf][k][row] + sW 2x16K.
// --------------------------------------------------------------------------
__global__ __launch_bounds__(512, 2) void lstm_kernel(LstmParams P) {
    int lstm = blockIdx.y;
    int n0 = blockIdx.x * 32;

    const float4* __restrict__ W4   = g_W4[lstm];
    const float*  __restrict__ bias = P.bias[lstm];
    const float*  __restrict__ xT   = g_xT[lstm >> 1];
    float*        __restrict__ Hout = g_H[lstm];
    const bool rev = (lstm & 1) != 0;

    extern __shared__ float sm[];
    float*  sX = sm;                          // [128][32]      (16 KB)
    float*  sH = sm + 4096;                   // [2][128][32]   (32 KB)
    float4* sW = (float4*)(sm + 12288);       // [2][8][128]    (32 KB)
    unsigned sWu = smem_u32(sW);

    int tid = threadIdx.x;
    int ch = tid & 127;
    int rg = tid >> 7;          // 0..3
    int r0 = rg * 8;

    float bi_f = bias[ch];
    float bf_f = bias[ch + 128];
    float bg_f = bias[ch + 256];
    float bo_f = bias[ch + 384];

    float c[8];
    #pragma unroll
    for (int r = 0; r < 8; r++) c[r] = 0.f;

    // zero h buffer 0 (h[-1]); stage x(0); prefetch weight chunk 0
    #pragma unroll
    for (int r = 0; r < 8; r++) sH[ch * 32 + r0 + r] = 0.f;
    {
        int t0 = rev ? 63 : 0;
        const float* xsrc = xT + ((size_t)(n0 + r0) * 64 + t0) * 128 + ch;
        #pragma unroll
        for (int r = 0; r < 8; r++)
            sX[ch * 32 + r0 + r] = xsrc[(size_t)r * 8192];
    }
    cp16(sWu + (unsigned)tid * 16, W4 + tid);
    cp16(sWu + (unsigned)(tid + 512) * 16, W4 + tid + 512);
    CP_COMMIT();

    for (int tt = 0; tt < 64; ++tt) {
        int t = rev ? 63 - tt : tt;
        int hbuf = tt & 1;

        ull ai[4], af[4], ag[4], ao[4];
        {
            ull bi = dup2(bi_f), bf = dup2(bf_f), bg = dup2(bg_f), bo = dup2(bo_f);
            #pragma unroll
            for (int rp = 0; rp < 4; rp++) { ai[rp] = bi; af[rp] = bf; ag[rp] = bg; ao[rp] = bo; }
        }

        for (int cc = 0; cc < 32; ++cc) {
            CP_WAIT0();          // chunk cc resident in sW[cc&1]
            __syncthreads();     // + orders x-stage / h-writes at cc==0

            // prefetch chunk (cc+1)&31 into the other buffer
            {
                int nc = (cc + 1) & 31;
                const float4* src = W4 + nc * 1024 + tid;
                unsigned dst = sWu + (unsigned)((((nc & 1) << 10) + tid) * 16);
                cp16(dst, src);
                cp16(dst + 512 * 16, src + 512);
                CP_COMMIT();
            }

            const float* vb = (cc < 16) ? (sX + cc * 256)
                                        : (sH + hbuf * 4096 + (cc - 16) * 256);
            const float4* wb = sW + ((cc & 1) << 10);

            #pragma unroll
            for (int k8 = 0; k8 < 8; ++k8) {
                float4 w = wb[k8 * 128 + ch];                 // LDS.128, conflict-free
                ull wi = dup2(w.x), wf = dup2(w.y), wg = dup2(w.z), wo = dup2(w.w);
                const ulonglong2* vp = (const ulonglong2*)(vb + k8 * 32 + rg * 8);
                ulonglong2 vA = vp[0];                        // row-pairs 0,1 (broadcast)
                ulonglong2 vB = vp[1];                        // row-pairs 2,3
                fma2(ai[0], vA.x, wi); fma2(af[0], vA.x, wf); fma2(ag[0], vA.x, wg); fma2(ao[0], vA.x, wo);
                fma2(ai[1], vA.y, wi); fma2(af[1], vA.y, wf); fma2(ag[1], vA.y, wg); fma2(ao[1], vA.y, wo);
                fma2(ai[2], vB.x, wi); fma2(af[2], vB.x, wf); fma2(ag[2], vB.x, wg); fma2(ao[2], vB.x, wo);
                fma2(ai[3], vB.y, wi); fma2(af[3], vB.y, wf); fma2(ag[3], vB.y, wg); fma2(ao[3], vB.y, wo);
            }
        }

        // ---- gate combine, fully local; h[t] -> other h buffer + gmem ----
        float* __restrict__ Hn = sH + (hbuf ^ 1) * 4096;
        #pragma unroll
        for (int rp = 0; rp < 4; rp++) {
            float2 zi = unpack2(ai[rp]);
            float2 zf = unpack2(af[rp]);
            float2 zg = unpack2(ag[rp]);
            float2 zo = unpack2(ao[rp]);

            int row = r0 + 2 * rp;
            c[2 * rp]     = sigf(zf.x) * c[2 * rp]     + sigf(zi.x) * tanhf_(zg.x);
            c[2 * rp + 1] = sigf(zf.y) * c[2 * rp + 1] + sigf(zi.y) * tanhf_(zg.y);
            float h0 = sigf(zo.x) * tanhf_(c[2 * rp]);
            float h1 = sigf(zo.y) * tanhf_(c[2 * rp + 1]);

            Hn[ch * 32 + row]     = h0;
            Hn[ch * 32 + row + 1] = h1;
            Hout[((size_t)(n0 + row) * 64 + t) * 128 + ch]     = h0;   // coalesced
            Hout[((size_t)(n0 + row + 1) * 64 + t) * 128 + ch] = h1;
        }

        // stage x for next step (chunks 16..31 of this step never read sX;
        // next step's cc==0 barrier orders these writes before reads)
        {
            int ttn = (tt < 63) ? tt + 1 : 63;
            int tn = rev ? 63 - ttn : ttn;
            const float* xsrc = xT + ((size_t)(n0 + r0) * 64 + tn) * 128 + ch;
            #pragma unroll
            for (int r = 0; r < 8; r++)
                sX[ch * 32 + r0 + r] = xsrc[(size_t)r * 8192];
        }
    }
    CP_WAIT0();   // drain the final (unused) prefetch before exit
}

// --------------------------------------------------------------------------
// Kernel 3: 1x1 conv with FFMA2. grid = (4096 tiles, 4 outputs), 128 threads.
// CTA: 32 positions x 128 outs. Thread: 4 outs x 4 position-pairs (16 f32x2).
// Hs stored transposed [c][pos] (pad 34) so a position-pair is one LDS.64.
// --------------------------------------------------------------------------
__global__ __launch_bounds__(128) void conv_kernel(ConvParams P, float* __restrict__ out) {
    int kk = blockIdx.y;                                  // 0:down 1:up 2:right 3:left
    int src = (kk == 0) ? 1 : ((kk == 1) ? 0 : kk);       // down<-vb, up<-vf, right<-hf, left<-hb
    const float*  __restrict__ Hg   = g_H[src];
    const float4* __restrict__ W4   = g_Wc4[kk];
    const float*  __restrict__ bias = P.b[kk];
    float* __restrict__ outk = out + (size_t)kk * NPLANE;

    __shared__ float Hs[128 * 34];                        // [c][pos], pad 34
    int tid = threadIdx.x;
    int p0 = blockIdx.x * 32;

    for (int idx = tid; idx < 32 * 128; idx += 128) {
        int p = idx >> 7, c = idx & 127;                  // coalesced gmem read
        Hs[c * 34 + p] = Hg[(size_t)(p0 + p) * 128 + c];
    }
    __syncthreads();

    int tp = tid & 3;    // pair base: pairs {tp, tp+4, tp+8, tp+12}
    int to = tid >> 2;   // outs: {to, to+32, to+64, to+96}

    ull acc[4][4];       // [out][pair]
    {
        ull b0 = dup2(bias[to]);
        ull b1 = dup2(bias[to + 32]);
        ull b2 = dup2(bias[to + 64]);
        ull b3 = dup2(bias[to + 96]);
        #pragma unroll
        for (int i = 0; i < 4; i++) { acc[0][i] = b0; acc[1][i] = b1; acc[2][i] = b2; acc[3][i] = b3; }
    }

    #pragma unroll 4
    for (int k = 0; k < 128; k++) {
        float4 w = W4[k * 32 + to];
        ull w0 = dup2(w.x), w1 = dup2(w.y), w2 = dup2(w.z), w3 = dup2(w.w);
        const ull* hp = (const ull*)(Hs + k * 34) + tp;
        #pragma unroll
        for (int i = 0; i < 4; i++) {
            ull v = hp[i * 4];
            fma2(acc[0][i], v, w0);
            fma2(acc[1][i], v, w1);
            fma2(acc[2][i], v, w2);
            fma2(acc[3][i], v, w3);
        }
    }

    #pragma unroll
    for (int i = 0; i < 4; i++) {
        int p = p0 + 2 * (tp + 4 * i);
        int b = p >> 12, q = p & 4095;
        float* ob = outk + (size_t)b * 128 * 4096 + q;
        #pragma unroll
        for (int j = 0; j < 4; j++) {
            float2 z = unpack2(acc[j][i]);
            *(float2*)(ob + (size_t)(to + 32 * j) * 4096) = z;   // STG.64, 8B-aligned
        }
    }
}

// --------------------------------------------------------------------------
// Launch. Inputs (metadata order):
// 0:x  1-3:vWih_f,vWhh_f,vb_f  4-6:vWih_b,vWhh_b,vb_b
// 7-9:hWih_f,hWhh_f,hb_f  10-12:hWih_b,hWhh_b,hb_b
// 13..20: (w,b) for down, up, right, left
// --------------------------------------------------------------------------
extern "C" void kernel_launch(void* const* d_in, const int* in_sizes, int n_in,
                              void* d_out, int out_size) {
    (void)in_sizes; (void)n_in; (void)out_size;
    const float* x = (const float*)d_in[0];

    LstmParams LP;
    for (int l = 0; l < 4; l++) {
        LP.Wih[l]  = (const float*)d_in[1 + 3 * l];
        LP.Whh[l]  = (const float*)d_in[2 + 3 * l];
        LP.bias[l] = (const float*)d_in[3 + 3 * l];
    }
    ConvParams CP;
    for (int k = 0; k < 4; k++) {
        CP.w[k] = (const float*)d_in[13 + 2 * k];
        CP.b[k] = (const float*)d_in[14 + 2 * k];
    }

    cudaFuncSetAttribute(lstm_kernel, cudaFuncAttributeMaxDynamicSharedMemorySize, 81920);

    pack_lstm_kernel<<<dim3(128, 4), 256>>>(LP);
    pack_conv_kernel<<<dim3(16, 4), 256>>>(CP);
    transpose_kernel<<<2048, 256>>>(x);
    lstm_kernel<<<dim3(64, 4), 512, 81920>>>(LP);
    conv_kernel<<<dim3(4096, 4), 128>>>(CP, (float*)d_out);
}